// round 10
// baseline (speedup 1.0000x reference)
#include <cuda_runtime.h>
#include <cuda_fp16.h>
#include <cstdint>

// Fused: out = swish(mult_w * swish(groupnorm(x @ W^T + b)))
// x:[4096,2048] W:[8192,2048] -> out:[4096,8192], 16 groups of 512 features.
//
// R9: explicit software pipeline of MMA fragments. R8 showed tensor=50% with
// LDSM->MMA serialization per ks step (no reg room for ptxas to pipeline).
// Double-buffer A/B ldmatrix fragments: issue ks+1 loads before ks MMAs.
// - fp16 m16n8k16 (2x tf32 rate, same 10-bit mantissa; fp32 accum)
// - pre-pass converts x,W fp32->fp16 into __device__ scratch
// - CTA 128x256 (half group), 512 thr, warp tile 32x64, cluster-2 DSMEM stats
// - cp.async 3-stage pipeline, KC=64, smem row stride 144B (conflict-free)

static constexpr int K_DIM  = 2048;
static constexpr int N_DIM  = 8192;
static constexpr int M_DIM  = 4096;
static constexpr int TILE_M = 128;
static constexpr int TILE_N = 256;
static constexpr int KC     = 64;
static constexpr int KTILES = K_DIM / KC;      // 32
static constexpr int THREADS = 512;
static constexpr int GRID = (M_DIM / TILE_M) * (N_DIM / TILE_N); // 1024

static constexpr int ROWB   = 144;             // 128B data + 16B pad
static constexpr int A_BYTES = TILE_M * ROWB;              // 18432
static constexpr int B_BYTES = TILE_N * ROWB;              // 36864
static constexpr int STAGE_BYTES = A_BYTES + B_BYTES;      // 55296
static constexpr int NSTAGES = 3;

static constexpr int SM_PARAM = NSTAGES * STAGE_BYTES;        // 165888
static constexpr int SM_RED   = SM_PARAM + 4 * TILE_N * 4;    // 169984
static constexpr int SM_STATS = SM_RED + 2 * TILE_M * 4;      // 171008
static constexpr int SMEM_TOTAL = SM_STATS + 2 * TILE_M * 4;  // 172032

__device__ __half g_x16[(size_t)M_DIM * K_DIM];   // 16 MB
__device__ __half g_w16[(size_t)N_DIM * K_DIM];   // 32 MB

#define DEVFN __device__ __forceinline__

DEVFN uint32_t s2u(const void* p) {
    uint32_t a;
    asm("{ .reg .u64 t; cvta.to.shared.u64 t, %1; cvt.u32.u64 %0, t; }" : "=r"(a) : "l"(p));
    return a;
}

DEVFN void mma_f16(float c[4], const uint32_t a[4], const uint32_t b[2]) {
    asm volatile(
        "mma.sync.aligned.m16n8k16.row.col.f32.f16.f16.f32 "
        "{%0,%1,%2,%3}, {%4,%5,%6,%7}, {%8,%9}, {%0,%1,%2,%3};"
        : "+f"(c[0]), "+f"(c[1]), "+f"(c[2]), "+f"(c[3])
        : "r"(a[0]), "r"(a[1]), "r"(a[2]), "r"(a[3]), "r"(b[0]), "r"(b[1]));
}

DEVFN void ldsm4(uint32_t r[4], uint32_t addr) {
    asm volatile(
        "ldmatrix.sync.aligned.m8n8.x4.shared.b16 {%0,%1,%2,%3}, [%4];"
        : "=r"(r[0]), "=r"(r[1]), "=r"(r[2]), "=r"(r[3]) : "r"(addr));
}

DEVFN void cp16(uint32_t dst, const void* src) {
    asm volatile("cp.async.cg.shared.global [%0], [%1], 16;" :: "r"(dst), "l"(src));
}

// ---- pre-pass: fp32 -> fp16 for x and W ----
__global__ void __launch_bounds__(256)
convert_f32_to_f16(const float* __restrict__ x, const float* __restrict__ W)
{
    const size_t XN4 = (size_t)M_DIM * K_DIM / 4;
    const size_t WN4 = (size_t)N_DIM * K_DIM / 4;
    const size_t total = XN4 + WN4;
    const size_t stride = (size_t)gridDim.x * blockDim.x;
    for (size_t i = (size_t)blockIdx.x * blockDim.x + threadIdx.x; i < total; i += stride) {
        float4 v;
        __half2* dst;
        if (i < XN4) {
            v = ((const float4*)x)[i];
            dst = (__half2*)g_x16 + i * 2;
        } else {
            v = ((const float4*)W)[i - XN4];
            dst = (__half2*)g_w16 + (i - XN4) * 2;
        }
        dst[0] = __floats2half2_rn(v.x, v.y);
        dst[1] = __floats2half2_rn(v.z, v.w);
    }
}

__global__ void __launch_bounds__(THREADS, 1) __cluster_dims__(2, 1, 1)
fused_gemm_gn_silu(const float* __restrict__ b, const float* __restrict__ gnw,
                   const float* __restrict__ gnb, const float* __restrict__ mw,
                   float* __restrict__ out)
{
    extern __shared__ char smem[];
    const uint32_t sb = s2u(smem);
    const int tid  = threadIdx.x;
    const int wid  = tid >> 5, lane = tid & 31;
    const int gid  = lane >> 2, ctid = lane & 3;
    const int wm   = wid & 3;        // 0..3 : 32-row band
    const int wn   = wid >> 2;       // 0..3 : 64-col band

    const int bx   = blockIdx.x;
    const int half = bx & 1;                 // cluster rank
    const int bm   = (bx >> 1) & 31;         // M block
    const int g    = bx >> 6;                // group 0..15
    const int nbase = g * 512 + half * TILE_N;

    float* bias_s = (float*)(smem + SM_PARAM);
    float* gnw_s  = bias_s + TILE_N;
    float* gnb_s  = gnw_s + TILE_N;
    float* mw_s   = gnb_s + TILE_N;
    float* red_s  = (float*)(smem + SM_RED);
    float* mean_s = (float*)(smem + SM_STATS);
    float* rstd_s = mean_s + TILE_M;

    if (tid < TILE_N) {
        bias_s[tid] = b[nbase + tid];
        gnw_s[tid]  = gnw[nbase + tid];
        gnb_s[tid]  = gnb[nbase + tid];
        mw_s[tid]   = mw[nbase + tid];
        red_s[tid]  = 0.f;
    }

    const __half* Abase = g_x16 + (size_t)bm * TILE_M * K_DIM;
    const __half* Bbase = g_w16 + (size_t)nbase * K_DIM;

    auto load_stage = [&](int kt, int slot) {
        const int k0 = kt * KC;
        const uint32_t abuf = sb + slot * STAGE_BYTES;
        const uint32_t bbuf = abuf + A_BYTES;
#pragma unroll
        for (int i = 0; i < 2; i++) {          // A: 128 rows x 8 chunks = 1024
            int ch = tid + i * THREADS;
            int r = ch >> 3, j = ch & 7;
            cp16(abuf + r * ROWB + j * 16, Abase + (size_t)r * K_DIM + k0 + j * 8);
        }
#pragma unroll
        for (int i = 0; i < 4; i++) {          // B: 256 rows x 8 chunks = 2048
            int ch = tid + i * THREADS;
            int r = ch >> 3, j = ch & 7;
            cp16(bbuf + r * ROWB + j * 16, Bbase + (size_t)r * K_DIM + k0 + j * 8);
        }
        asm volatile("cp.async.commit_group;" ::: "memory");
    };

    // ldmatrix lane offsets (b16 tiles, 16B per 8x8 tile row)
    const int lq = lane >> 3, lr = lane & 7;
    const uint32_t a_lane = (uint32_t)((((lq & 1) * 8 + lr) * ROWB) + (lq >> 1) * 16);
    const uint32_t b_lane = (uint32_t)((((lq >> 1) * 8 + lr) * ROWB) + (lq & 1) * 16);
    const uint32_t a_warp = (uint32_t)(wm * 32 * ROWB) + a_lane;
    const uint32_t b_warp = (uint32_t)(A_BYTES + wn * 64 * ROWB) + b_lane;

    float acc[2][8][4];
#pragma unroll
    for (int i = 0; i < 2; i++)
#pragma unroll
        for (int j = 0; j < 8; j++)
#pragma unroll
            for (int r = 0; r < 4; r++) acc[i][j][r] = 0.f;

    load_stage(0, 0);
    load_stage(1, 1);

    for (int t = 0; t < KTILES; t++) {
        asm volatile("cp.async.wait_group 1;" ::: "memory");
        __syncthreads();
        if (t + 2 < KTILES) load_stage(t + 2, (t + 2) % NSTAGES);

        const uint32_t stage = sb + (t % NSTAGES) * STAGE_BYTES;
        const uint32_t aaddr = stage + a_warp;
        const uint32_t baddr = stage + b_warp;

        // software-pipelined fragment loads: double-buffered A and B frags
        uint32_t afr[2][2][4];     // [buf][i]
        uint32_t bfr[2][4][4];     // [buf][jp]
#pragma unroll
        for (int i = 0; i < 2; i++)
            ldsm4(afr[0][i], aaddr + i * 16 * ROWB);
#pragma unroll
        for (int jp = 0; jp < 4; jp++)
            ldsm4(bfr[0][jp], baddr + jp * 16 * ROWB);

#pragma unroll
        for (int ks = 0; ks < 4; ks++) {       // 4 chunks of k16, 32B each
            const int cur = ks & 1, nxt = cur ^ 1;
            if (ks < 3) {
#pragma unroll
                for (int i = 0; i < 2; i++)
                    ldsm4(afr[nxt][i], aaddr + i * 16 * ROWB + (ks + 1) * 32);
#pragma unroll
                for (int jp = 0; jp < 4; jp++)
                    ldsm4(bfr[nxt][jp], baddr + jp * 16 * ROWB + (ks + 1) * 32);
            }
#pragma unroll
            for (int i = 0; i < 2; i++)
#pragma unroll
                for (int j = 0; j < 8; j++)
                    mma_f16(acc[i][j], afr[cur][i], &bfr[cur][j >> 1][(j & 1) * 2]);
        }
    }
    asm volatile("cp.async.wait_group 0;" ::: "memory");
    __syncthreads();

    // ---- bias add + per-thread partial stats ----
    float psum0[2], psq0[2], psum1[2], psq1[2];
#pragma unroll
    for (int i = 0; i < 2; i++) { psum0[i] = psq0[i] = psum1[i] = psq1[i] = 0.f; }
#pragma unroll
    for (int i = 0; i < 2; i++) {
#pragma unroll
        for (int j = 0; j < 8; j++) {
            const int nc = wn * 64 + j * 8 + 2 * ctid;
            float y0 = acc[i][j][0] + bias_s[nc];
            float y1 = acc[i][j][1] + bias_s[nc + 1];
            float y2 = acc[i][j][2] + bias_s[nc];
            float y3 = acc[i][j][3] + bias_s[nc + 1];
            acc[i][j][0] = y0; acc[i][j][1] = y1; acc[i][j][2] = y2; acc[i][j][3] = y3;
            psum0[i] += y0 + y1;  psq0[i] += y0 * y0 + y1 * y1;
            psum1[i] += y2 + y3;  psq1[i] += y2 * y2 + y3 * y3;
        }
    }
#pragma unroll
    for (int i = 0; i < 2; i++) {
#pragma unroll
        for (int d = 1; d < 4; d <<= 1) {
            psum0[i] += __shfl_xor_sync(0xffffffffu, psum0[i], d);
            psq0[i]  += __shfl_xor_sync(0xffffffffu, psq0[i], d);
            psum1[i] += __shfl_xor_sync(0xffffffffu, psum1[i], d);
            psq1[i]  += __shfl_xor_sync(0xffffffffu, psq1[i], d);
        }
        if (ctid == 0) {
            const int r0 = wm * 32 + i * 16 + gid;
            atomicAdd(&red_s[r0], psum0[i]);
            atomicAdd(&red_s[TILE_M + r0], psq0[i]);
            atomicAdd(&red_s[r0 + 8], psum1[i]);
            atomicAdd(&red_s[TILE_M + r0 + 8], psq1[i]);
        }
    }
    __syncthreads();

    // ---- cluster exchange of per-row partials ----
    uint32_t myrank;
    asm("mov.u32 %0, %%cluster_ctarank;" : "=r"(myrank));
    const uint32_t peer = myrank ^ 1u;

    asm volatile("barrier.cluster.arrive.aligned;" ::: "memory");
    asm volatile("barrier.cluster.wait.aligned;" ::: "memory");

    if (tid < TILE_M) {
        const uint32_t lsum = sb + SM_RED + tid * 4;
        const uint32_t lsq  = lsum + TILE_M * 4;
        uint32_t rsum, rsq;
        asm("mapa.shared::cluster.u32 %0, %1, %2;" : "=r"(rsum) : "r"(lsum), "r"(peer));
        asm("mapa.shared::cluster.u32 %0, %1, %2;" : "=r"(rsq)  : "r"(lsq),  "r"(peer));
        float ps, pq;
        asm volatile("ld.shared::cluster.f32 %0, [%1];" : "=f"(ps) : "r"(rsum));
        asm volatile("ld.shared::cluster.f32 %0, [%1];" : "=f"(pq) : "r"(rsq));
        const float s  = red_s[tid] + ps;
        const float sq = red_s[TILE_M + tid] + pq;
        const float mean = s * (1.0f / 512.0f);
        const float var  = fmaxf(sq * (1.0f / 512.0f) - mean * mean, 0.f);
        mean_s[tid] = mean;
        rstd_s[tid] = rsqrtf(var + 1e-5f);
    }
    __syncthreads();
    asm volatile("barrier.cluster.arrive.aligned;" ::: "memory");

    // ---- normalize + SiLU chain + store ----
    float* obase = out + (size_t)(bm * TILE_M) * N_DIM + nbase;
#pragma unroll
    for (int i = 0; i < 2; i++) {
        const int r0 = wm * 32 + i * 16 + gid;
        const float m0 = mean_s[r0],     rs0 = rstd_s[r0];
        const float m1 = mean_s[r0 + 8], rs1 = rstd_s[r0 + 8];
#pragma unroll
        for (int j = 0; j < 8; j++) {
            const int nc = wn * 64 + j * 8 + 2 * ctid;
            const float gw0 = gnw_s[nc], gw1 = gnw_s[nc + 1];
            const float gb0 = gnb_s[nc], gb1 = gnb_s[nc + 1];
            const float w0  = mw_s[nc],  w1  = mw_s[nc + 1];
            float v[4];
            {
                float t0 = (acc[i][j][0] - m0) * rs0 * gw0 + gb0;
                float t1 = (acc[i][j][1] - m0) * rs0 * gw1 + gb1;
                float t2 = (acc[i][j][2] - m1) * rs1 * gw0 + gb0;
                float t3 = (acc[i][j][3] - m1) * rs1 * gw1 + gb1;
                float s0 = t0 / (1.f + __expf(-t0)) * w0;
                float s1 = t1 / (1.f + __expf(-t1)) * w1;
                float s2 = t2 / (1.f + __expf(-t2)) * w0;
                float s3 = t3 / (1.f + __expf(-t3)) * w1;
                v[0] = s0 / (1.f + __expf(-s0));
                v[1] = s1 / (1.f + __expf(-s1));
                v[2] = s2 / (1.f + __expf(-s2));
                v[3] = s3 / (1.f + __expf(-s3));
            }
            float2* p0 = (float2*)(obase + (size_t)r0 * N_DIM + nc);
            float2* p1 = (float2*)(obase + (size_t)(r0 + 8) * N_DIM + nc);
            *p0 = make_float2(v[0], v[1]);
            *p1 = make_float2(v[2], v[3]);
        }
    }

    asm volatile("barrier.cluster.wait.aligned;" ::: "memory");
}

extern "C" void kernel_launch(void* const* d_in, const int* in_sizes, int n_in,
                              void* d_out, int out_size)
{
    const float* x   = (const float*)d_in[0];
    const float* W   = (const float*)d_in[1];
    const float* b   = (const float*)d_in[2];
    const float* gnw = (const float*)d_in[3];
    const float* gnb = (const float*)d_in[4];
    const float* mw  = (const float*)d_in[5];
    float* out = (float*)d_out;

    convert_f32_to_f16<<<2048, 256>>>(x, W);

    cudaFuncSetAttribute(fused_gemm_gn_silu,
                         cudaFuncAttributeMaxDynamicSharedMemorySize, SMEM_TOTAL);
    fused_gemm_gn_silu<<<GRID, THREADS, SMEM_TOTAL>>>(b, gnw, gnb, mw, out);
}

// round 11
// speedup vs baseline: 1.2204x; 1.2204x over previous
#include <cuda_runtime.h>
#include <cuda_fp16.h>
#include <cstdint>

// Fused: out = swish(mult_w * swish(groupnorm(x @ W^T + b)))
// x:[4096,2048] W:[8192,2048] -> out:[4096,8192], 16 groups of 512 features.
//
// R10: break SM phase-lock. R8/R9 showed tensor~50%, L1~44%, k-tile time ~= sum
// of tensor + crossbar phases: 16 warps in ONE barrier domain alternate
// all-LDSM / all-MMA phases. Split into 2 CTAs/SM x 256 thr (two independent
// barrier domains) so one CTA's MMA phase overlaps the other's LDSM phase.
// - CTA tile 128x128, warp tile 32x64 (8 warps), fp16 m16n8k16, fp32 accum
// - XOR-swizzled 128B smem rows (no pad) -> stage 32KB, 3 stages, ~100KB/CTA
// - cluster of 4 CTAs = one group (4 N-quarters); stats via DSMEM from 3 peers
// - fp32->fp16 convert pre-pass into __device__ scratch

static constexpr int K_DIM  = 2048;
static constexpr int N_DIM  = 8192;
static constexpr int M_DIM  = 4096;
static constexpr int TILE_M = 128;
static constexpr int TILE_N = 128;
static constexpr int KC     = 64;
static constexpr int KTILES = K_DIM / KC;      // 32
static constexpr int THREADS = 256;
static constexpr int GRID = (M_DIM / TILE_M) * (N_DIM / TILE_N); // 32*64 = 2048

static constexpr int ROWB   = 128;             // 64 halves, no pad (XOR swizzle)
static constexpr int A_BYTES = TILE_M * ROWB;              // 16384
static constexpr int B_BYTES = TILE_N * ROWB;              // 16384
static constexpr int STAGE_BYTES = A_BYTES + B_BYTES;      // 32768
static constexpr int NSTAGES = 3;

static constexpr int SM_PARAM = NSTAGES * STAGE_BYTES;        // 98304
static constexpr int SM_RED   = SM_PARAM + 4 * TILE_N * 4;    // 100352
static constexpr int SM_STATS = SM_RED + 2 * TILE_M * 4;      // 101376
static constexpr int SMEM_TOTAL = SM_STATS + 2 * TILE_M * 4;  // 102400 (x2 CTA = 200KB)

__device__ __half g_x16[(size_t)M_DIM * K_DIM];   // 16 MB
__device__ __half g_w16[(size_t)N_DIM * K_DIM];   // 32 MB

#define DEVFN __device__ __forceinline__

DEVFN uint32_t s2u(const void* p) {
    uint32_t a;
    asm("{ .reg .u64 t; cvta.to.shared.u64 t, %1; cvt.u32.u64 %0, t; }" : "=r"(a) : "l"(p));
    return a;
}

DEVFN void mma_f16(float c[4], const uint32_t a[4], const uint32_t b[2]) {
    asm volatile(
        "mma.sync.aligned.m16n8k16.row.col.f32.f16.f16.f32 "
        "{%0,%1,%2,%3}, {%4,%5,%6,%7}, {%8,%9}, {%0,%1,%2,%3};"
        : "+f"(c[0]), "+f"(c[1]), "+f"(c[2]), "+f"(c[3])
        : "r"(a[0]), "r"(a[1]), "r"(a[2]), "r"(a[3]), "r"(b[0]), "r"(b[1]));
}

DEVFN void ldsm4(uint32_t r[4], uint32_t addr) {
    asm volatile(
        "ldmatrix.sync.aligned.m8n8.x4.shared.b16 {%0,%1,%2,%3}, [%4];"
        : "=r"(r[0]), "=r"(r[1]), "=r"(r[2]), "=r"(r[3]) : "r"(addr));
}

DEVFN void cp16(uint32_t dst, const void* src) {
    asm volatile("cp.async.cg.shared.global [%0], [%1], 16;" :: "r"(dst), "l"(src));
}

// ---- pre-pass: fp32 -> fp16 for x and W ----
__global__ void __launch_bounds__(256)
convert_f32_to_f16(const float* __restrict__ x, const float* __restrict__ W)
{
    const size_t XN4 = (size_t)M_DIM * K_DIM / 4;
    const size_t WN4 = (size_t)N_DIM * K_DIM / 4;
    const size_t total = XN4 + WN4;
    const size_t stride = (size_t)gridDim.x * blockDim.x;
    for (size_t i = (size_t)blockIdx.x * blockDim.x + threadIdx.x; i < total; i += stride) {
        float4 v;
        __half2* dst;
        if (i < XN4) {
            v = ((const float4*)x)[i];
            dst = (__half2*)g_x16 + i * 2;
        } else {
            v = ((const float4*)W)[i - XN4];
            dst = (__half2*)g_w16 + (i - XN4) * 2;
        }
        dst[0] = __floats2half2_rn(v.x, v.y);
        dst[1] = __floats2half2_rn(v.z, v.w);
    }
}

__global__ void __launch_bounds__(THREADS, 2) __cluster_dims__(4, 1, 1)
fused_gemm_gn_silu(const float* __restrict__ b, const float* __restrict__ gnw,
                   const float* __restrict__ gnb, const float* __restrict__ mw,
                   float* __restrict__ out)
{
    extern __shared__ char smem[];
    const uint32_t sb = s2u(smem);
    const int tid  = threadIdx.x;
    const int wid  = tid >> 5, lane = tid & 31;
    const int gid  = lane >> 2, ctid = lane & 3;
    const int wm   = wid & 3;        // 0..3 : 32-row band
    const int wn   = wid >> 2;       // 0..1 : 64-col band

    const int bx   = blockIdx.x;
    const int rank = bx & 3;                 // cluster rank = N quarter
    const int bm   = (bx >> 2) & 31;         // M block
    const int g    = bx >> 7;                // group 0..15
    const int nbase = g * 512 + rank * TILE_N;

    float* bias_s = (float*)(smem + SM_PARAM);
    float* gnw_s  = bias_s + TILE_N;
    float* gnb_s  = gnw_s + TILE_N;
    float* mw_s   = gnb_s + TILE_N;
    float* red_s  = (float*)(smem + SM_RED);     // [0..127]=sum, [128..255]=sq
    float* mean_s = (float*)(smem + SM_STATS);
    float* rstd_s = mean_s + TILE_M;

    if (tid < TILE_N) {
        bias_s[tid] = b[nbase + tid];
        gnw_s[tid]  = gnw[nbase + tid];
        gnb_s[tid]  = gnb[nbase + tid];
        mw_s[tid]   = mw[nbase + tid];
    }
    red_s[tid] = 0.f;   // 256 entries, 256 threads

    const __half* Abase = g_x16 + (size_t)bm * TILE_M * K_DIM;
    const __half* Bbase = g_w16 + (size_t)nbase * K_DIM;

    // stage fill: row r (128B = 8 x 16B chunks), chunk j stored at (j ^ (r&7))
    auto load_stage = [&](int kt, int slot) {
        const int k0 = kt * KC;
        const uint32_t abuf = sb + slot * STAGE_BYTES;
        const uint32_t bbuf = abuf + A_BYTES;
#pragma unroll
        for (int i = 0; i < 4; i++) {          // A: 128 rows x 8 chunks = 1024
            int ch = tid + i * THREADS;
            int r = ch >> 3, j = ch & 7;
            cp16(abuf + r * ROWB + ((j ^ (r & 7)) << 4),
                 Abase + (size_t)r * K_DIM + k0 + j * 8);
        }
#pragma unroll
        for (int i = 0; i < 4; i++) {          // B: 128 rows x 8 chunks = 1024
            int ch = tid + i * THREADS;
            int r = ch >> 3, j = ch & 7;
            cp16(bbuf + r * ROWB + ((j ^ (r & 7)) << 4),
                 Bbase + (size_t)r * K_DIM + k0 + j * 8);
        }
        asm volatile("cp.async.commit_group;" ::: "memory");
    };

    // ldmatrix lane addressing with swizzle.
    // A x4 tiles: m0=(rows+0..7,klo) m1=(rows+8..15,klo) m2=(+0..7,khi) m3=(+8..15,khi)
    //   row = base + (lq&1)*8 + lr, chunk = 2ks + (lq>>1); row&7 == lr.
    // B x4 tiles: m0=(n+0..7,klo) m1=(n+0..7,khi) m2=(n+8..15,klo) m3=(n+8..15,khi)
    //   row = base + (lq>>1)*8 + lr, chunk = 2ks + (lq&1); row&7 == lr.
    const int lq = lane >> 3, lr = lane & 7;
    const uint32_t cba = lq >> 1, cbb = lq & 1;
    uint32_t raoff[2], rboff[4], swzA[4], swzB[4];
#pragma unroll
    for (int i = 0; i < 2; i++)
        raoff[i] = (uint32_t)((wm * 32 + i * 16 + (lq & 1) * 8 + lr) * ROWB);
#pragma unroll
    for (int jp = 0; jp < 4; jp++)
        rboff[jp] = (uint32_t)(A_BYTES + (wn * 64 + jp * 16 + (lq >> 1) * 8 + lr) * ROWB);
#pragma unroll
    for (int ks = 0; ks < 4; ks++) {
        swzA[ks] = (uint32_t)(((2 * ks + cba) ^ lr) << 4);
        swzB[ks] = (uint32_t)(((2 * ks + cbb) ^ lr) << 4);
    }

    float acc[2][8][4];
#pragma unroll
    for (int i = 0; i < 2; i++)
#pragma unroll
        for (int j = 0; j < 8; j++)
#pragma unroll
            for (int r = 0; r < 4; r++) acc[i][j][r] = 0.f;

    load_stage(0, 0);
    load_stage(1, 1);

    for (int t = 0; t < KTILES; t++) {
        if (t == KTILES - 1) asm volatile("cp.async.wait_group 0;" ::: "memory");
        else                 asm volatile("cp.async.wait_group 1;" ::: "memory");
        __syncthreads();
        if (t + 2 < KTILES) load_stage(t + 2, (t + 2) % NSTAGES);

        const uint32_t stage = sb + (t % NSTAGES) * STAGE_BYTES;

#pragma unroll
        for (int ks = 0; ks < 4; ks++) {
            uint32_t afr[2][4];
#pragma unroll
            for (int i = 0; i < 2; i++)
                ldsm4(afr[i], stage + raoff[i] + swzA[ks]);
            uint32_t bfr[4][4];
#pragma unroll
            for (int jp = 0; jp < 4; jp++)
                ldsm4(bfr[jp], stage + rboff[jp] + swzB[ks]);
#pragma unroll
            for (int i = 0; i < 2; i++)
#pragma unroll
                for (int j = 0; j < 8; j++)
                    mma_f16(acc[i][j], afr[i], &bfr[j >> 1][(j & 1) * 2]);
        }
    }
    __syncthreads();

    // ---- bias add + per-thread partial stats ----
    float psum0[2], psq0[2], psum1[2], psq1[2];
#pragma unroll
    for (int i = 0; i < 2; i++) { psum0[i] = psq0[i] = psum1[i] = psq1[i] = 0.f; }
#pragma unroll
    for (int i = 0; i < 2; i++) {
#pragma unroll
        for (int j = 0; j < 8; j++) {
            const int nc = wn * 64 + j * 8 + 2 * ctid;
            float y0 = acc[i][j][0] + bias_s[nc];
            float y1 = acc[i][j][1] + bias_s[nc + 1];
            float y2 = acc[i][j][2] + bias_s[nc];
            float y3 = acc[i][j][3] + bias_s[nc + 1];
            acc[i][j][0] = y0; acc[i][j][1] = y1; acc[i][j][2] = y2; acc[i][j][3] = y3;
            psum0[i] += y0 + y1;  psq0[i] += y0 * y0 + y1 * y1;
            psum1[i] += y2 + y3;  psq1[i] += y2 * y2 + y3 * y3;
        }
    }
#pragma unroll
    for (int i = 0; i < 2; i++) {
#pragma unroll
        for (int d = 1; d < 4; d <<= 1) {
            psum0[i] += __shfl_xor_sync(0xffffffffu, psum0[i], d);
            psq0[i]  += __shfl_xor_sync(0xffffffffu, psq0[i], d);
            psum1[i] += __shfl_xor_sync(0xffffffffu, psum1[i], d);
            psq1[i]  += __shfl_xor_sync(0xffffffffu, psq1[i], d);
        }
        if (ctid == 0) {
            const int r0 = wm * 32 + i * 16 + gid;
            atomicAdd(&red_s[r0], psum0[i]);
            atomicAdd(&red_s[TILE_M + r0], psq0[i]);
            atomicAdd(&red_s[r0 + 8], psum1[i]);
            atomicAdd(&red_s[TILE_M + r0 + 8], psq1[i]);
        }
    }
    __syncthreads();

    // ---- cluster exchange: combine per-row partials from 3 peers ----
    asm volatile("barrier.cluster.arrive.aligned;" ::: "memory");
    asm volatile("barrier.cluster.wait.aligned;" ::: "memory");

    if (tid < TILE_M) {
        float s  = red_s[tid];
        float sq = red_s[TILE_M + tid];
        const uint32_t lsum = sb + SM_RED + tid * 4;
        const uint32_t lsq  = lsum + TILE_M * 4;
#pragma unroll
        for (int p = 1; p < 4; p++) {
            const uint32_t peer = ((uint32_t)rank + p) & 3u;
            uint32_t rsum, rsq;
            asm("mapa.shared::cluster.u32 %0, %1, %2;" : "=r"(rsum) : "r"(lsum), "r"(peer));
            asm("mapa.shared::cluster.u32 %0, %1, %2;" : "=r"(rsq)  : "r"(lsq),  "r"(peer));
            float ps, pq;
            asm volatile("ld.shared::cluster.f32 %0, [%1];" : "=f"(ps) : "r"(rsum));
            asm volatile("ld.shared::cluster.f32 %0, [%1];" : "=f"(pq) : "r"(rsq));
            s += ps; sq += pq;
        }
        const float mean = s * (1.0f / 512.0f);
        const float var  = fmaxf(sq * (1.0f / 512.0f) - mean * mean, 0.f);
        mean_s[tid] = mean;
        rstd_s[tid] = rsqrtf(var + 1e-5f);
    }
    __syncthreads();
    asm volatile("barrier.cluster.arrive.aligned;" ::: "memory");

    // ---- normalize + SiLU chain + store ----
    float* obase = out + (size_t)(bm * TILE_M) * N_DIM + nbase;
#pragma unroll
    for (int i = 0; i < 2; i++) {
        const int r0 = wm * 32 + i * 16 + gid;
        const float m0 = mean_s[r0],     rs0 = rstd_s[r0];
        const float m1 = mean_s[r0 + 8], rs1 = rstd_s[r0 + 8];
#pragma unroll
        for (int j = 0; j < 8; j++) {
            const int nc = wn * 64 + j * 8 + 2 * ctid;
            const float gw0 = gnw_s[nc], gw1 = gnw_s[nc + 1];
            const float gb0 = gnb_s[nc], gb1 = gnb_s[nc + 1];
            const float w0  = mw_s[nc],  w1  = mw_s[nc + 1];
            float v[4];
            {
                float t0 = (acc[i][j][0] - m0) * rs0 * gw0 + gb0;
                float t1 = (acc[i][j][1] - m0) * rs0 * gw1 + gb1;
                float t2 = (acc[i][j][2] - m1) * rs1 * gw0 + gb0;
                float t3 = (acc[i][j][3] - m1) * rs1 * gw1 + gb1;
                float s0 = t0 / (1.f + __expf(-t0)) * w0;
                float s1 = t1 / (1.f + __expf(-t1)) * w1;
                float s2 = t2 / (1.f + __expf(-t2)) * w0;
                float s3 = t3 / (1.f + __expf(-t3)) * w1;
                v[0] = s0 / (1.f + __expf(-s0));
                v[1] = s1 / (1.f + __expf(-s1));
                v[2] = s2 / (1.f + __expf(-s2));
                v[3] = s3 / (1.f + __expf(-s3));
            }
            float2* p0 = (float2*)(obase + (size_t)r0 * N_DIM + nc);
            float2* p1 = (float2*)(obase + (size_t)(r0 + 8) * N_DIM + nc);
            *p0 = make_float2(v[0], v[1]);
            *p1 = make_float2(v[2], v[3]);
        }
    }

    asm volatile("barrier.cluster.wait.aligned;" ::: "memory");
}

extern "C" void kernel_launch(void* const* d_in, const int* in_sizes, int n_in,
                              void* d_out, int out_size)
{
    const float* x   = (const float*)d_in[0];
    const float* W   = (const float*)d_in[1];
    const float* b   = (const float*)d_in[2];
    const float* gnw = (const float*)d_in[3];
    const float* gnb = (const float*)d_in[4];
    const float* mw  = (const float*)d_in[5];
    float* out = (float*)d_out;

    convert_f32_to_f16<<<2048, 256>>>(x, W);

    cudaFuncSetAttribute(fused_gemm_gn_silu,
                         cudaFuncAttributeMaxDynamicSharedMemorySize, SMEM_TOTAL);
    fused_gemm_gn_silu<<<GRID, THREADS, SMEM_TOTAL>>>(b, gnw, gnb, mw, out);
}

// round 14
// speedup vs baseline: 1.2971x; 1.0629x over previous
#include <cuda_runtime.h>
#include <cuda_fp16.h>
#include <cstdint>

// Fused: out = swish(mult_w * swish(groupnorm(x @ W^T + b)))
// x:[4096,2048] W:[8192,2048] -> out:[4096,8192], 16 groups of 512 features.
//
// R11: warp-granular pipeline. R10 (2 CTAs/SM) validated phase-decorrelation;
// this round removes the per-k-tile __syncthreads and drives the 3-stage
// cp.async pipeline with per-stage mbarriers (full: 256 thread arrivals via
// cp.async.mbarrier.arrive; empty: 8 warp arrivals after last LDSM of stage).
// 16 warps/SM now slide independently (skew bound = 3 k-tiles).
// - CTA tile 128x128, warp tile 32x64, fp16 m16n8k16, fp32 accum
// - XOR-swizzled 128B smem rows, stage 32KB, 3 stages, 2 CTAs/SM
// - cluster of 4 CTAs = one group; stats via DSMEM
// - fp32->fp16 convert pre-pass into __device__ scratch

static constexpr int K_DIM  = 2048;
static constexpr int N_DIM  = 8192;
static constexpr int M_DIM  = 4096;
static constexpr int TILE_M = 128;
static constexpr int TILE_N = 128;
static constexpr int KC     = 64;
static constexpr int KTILES = K_DIM / KC;      // 32
static constexpr int THREADS = 256;
static constexpr int GRID = (M_DIM / TILE_M) * (N_DIM / TILE_N); // 2048

static constexpr int ROWB   = 128;
static constexpr int A_BYTES = TILE_M * ROWB;              // 16384
static constexpr int B_BYTES = TILE_N * ROWB;              // 16384
static constexpr int STAGE_BYTES = A_BYTES + B_BYTES;      // 32768
static constexpr int NSTAGES = 3;

static constexpr int SM_PARAM = NSTAGES * STAGE_BYTES;        // 98304
static constexpr int SM_RED   = SM_PARAM + 4 * TILE_N * 4;    // 100352
static constexpr int SM_STATS = SM_RED + 2 * TILE_M * 4;      // 101376
static constexpr int SM_MBAR  = SM_STATS + 2 * TILE_M * 4;    // 102400 (6 x 8B)
static constexpr int SMEM_TOTAL = SM_MBAR + 64;               // 102464 (x2 = 200.1KB)

__device__ __half g_x16[(size_t)M_DIM * K_DIM];   // 16 MB
__device__ __half g_w16[(size_t)N_DIM * K_DIM];   // 32 MB

#define DEVFN __device__ __forceinline__

DEVFN uint32_t s2u(const void* p) {
    uint32_t a;
    asm("{ .reg .u64 t; cvta.to.shared.u64 t, %1; cvt.u32.u64 %0, t; }" : "=r"(a) : "l"(p));
    return a;
}

DEVFN void mma_f16(float c[4], const uint32_t a[4], const uint32_t b[2]) {
    asm volatile(
        "mma.sync.aligned.m16n8k16.row.col.f32.f16.f16.f32 "
        "{%0,%1,%2,%3}, {%4,%5,%6,%7}, {%8,%9}, {%0,%1,%2,%3};"
        : "+f"(c[0]), "+f"(c[1]), "+f"(c[2]), "+f"(c[3])
        : "r"(a[0]), "r"(a[1]), "r"(a[2]), "r"(a[3]), "r"(b[0]), "r"(b[1]));
}

DEVFN void ldsm4(uint32_t r[4], uint32_t addr) {
    asm volatile(
        "ldmatrix.sync.aligned.m8n8.x4.shared.b16 {%0,%1,%2,%3}, [%4];"
        : "=r"(r[0]), "=r"(r[1]), "=r"(r[2]), "=r"(r[3]) : "r"(addr));
}

DEVFN void cp16(uint32_t dst, const void* src) {
    asm volatile("cp.async.cg.shared.global [%0], [%1], 16;" :: "r"(dst), "l"(src));
}

#define MBAR_INIT(addr, cnt) \
    asm volatile("mbarrier.init.shared.b64 [%0], %1;" :: "r"(addr), "r"((uint32_t)(cnt)) : "memory")

#define MBAR_WAIT(addr, parity) do { \
    asm volatile( \
        "{\n\t" \
        ".reg .pred P1;\n\t" \
        "WAIT_%=:\n\t" \
        "mbarrier.try_wait.parity.acquire.cta.shared::cta.b64 P1, [%0], %1, 0x989680;\n\t" \
        "@P1 bra.uni DONE_%=;\n\t" \
        "bra.uni WAIT_%=;\n\t" \
        "DONE_%=:\n\t" \
        "}" \
        :: "r"(addr), "r"((uint32_t)(parity)) : "memory"); \
} while (0)

// ---- pre-pass: fp32 -> fp16 for x and W ----
__global__ void __launch_bounds__(256)
convert_f32_to_f16(const float* __restrict__ x, const float* __restrict__ W)
{
    const size_t XN4 = (size_t)M_DIM * K_DIM / 4;
    const size_t WN4 = (size_t)N_DIM * K_DIM / 4;
    const size_t total = XN4 + WN4;
    const size_t stride = (size_t)gridDim.x * blockDim.x;
    for (size_t i = (size_t)blockIdx.x * blockDim.x + threadIdx.x; i < total; i += stride) {
        float4 v;
        __half2* dst;
        if (i < XN4) {
            v = ((const float4*)x)[i];
            dst = (__half2*)g_x16 + i * 2;
        } else {
            v = ((const float4*)W)[i - XN4];
            dst = (__half2*)g_w16 + (i - XN4) * 2;
        }
        dst[0] = __floats2half2_rn(v.x, v.y);
        dst[1] = __floats2half2_rn(v.z, v.w);
    }
}

__global__ void __launch_bounds__(THREADS, 2) __cluster_dims__(4, 1, 1)
fused_gemm_gn_silu(const float* __restrict__ b, const float* __restrict__ gnw,
                   const float* __restrict__ gnb, const float* __restrict__ mw,
                   float* __restrict__ out)
{
    extern __shared__ char smem[];
    const uint32_t sb = s2u(smem);
    const int tid  = threadIdx.x;
    const int wid  = tid >> 5, lane = tid & 31;
    const int gid  = lane >> 2, ctid = lane & 3;
    const int wm   = wid & 3;        // 0..3 : 32-row band
    const int wn   = wid >> 2;       // 0..1 : 64-col band

    const int bx   = blockIdx.x;
    const int rank = bx & 3;                 // cluster rank = N quarter
    const int bm   = (bx >> 2) & 31;         // M block
    const int g    = bx >> 7;                // group 0..15
    const int nbase = g * 512 + rank * TILE_N;

    float* bias_s = (float*)(smem + SM_PARAM);
    float* gnw_s  = bias_s + TILE_N;
    float* gnb_s  = gnw_s + TILE_N;
    float* mw_s   = gnb_s + TILE_N;
    float* red_s  = (float*)(smem + SM_RED);
    float* mean_s = (float*)(smem + SM_STATS);
    float* rstd_s = mean_s + TILE_M;

    const uint32_t fullb  = sb + SM_MBAR;       // 3 x 8B
    const uint32_t emptyb = sb + SM_MBAR + 24;  // 3 x 8B

    if (tid == 0) {
#pragma unroll
        for (int s = 0; s < 3; s++) {
            MBAR_INIT(fullb + 8 * s, THREADS);  // all threads' cp.async arrive
            MBAR_INIT(emptyb + 8 * s, 8);       // one arrive per warp
        }
    }
    if (tid < TILE_N) {
        bias_s[tid] = b[nbase + tid];
        gnw_s[tid]  = gnw[nbase + tid];
        gnb_s[tid]  = gnb[nbase + tid];
        mw_s[tid]   = mw[nbase + tid];
    }
    red_s[tid] = 0.f;
    __syncthreads();   // mbarrier init + red_s visible

    const __half* Abase = g_x16 + (size_t)bm * TILE_M * K_DIM;
    const __half* Bbase = g_w16 + (size_t)nbase * K_DIM;

    // produce tile u into slot u%3; wait for buffer free (empty) when reusing
    auto produce = [&](int u) {
        const int s2 = u % 3;
        if (u >= 3) MBAR_WAIT(emptyb + 8 * s2, ((u / 3 - 1) & 1));
        const int k0 = u * KC;
        const uint32_t abuf = sb + s2 * STAGE_BYTES;
        const uint32_t bbuf = abuf + A_BYTES;
#pragma unroll
        for (int i = 0; i < 4; i++) {          // A: 128 rows x 8 chunks
            int ch = tid + i * THREADS;
            int r = ch >> 3, j = ch & 7;
            cp16(abuf + r * ROWB + ((j ^ (r & 7)) << 4),
                 Abase + (size_t)r * K_DIM + k0 + j * 8);
        }
#pragma unroll
        for (int i = 0; i < 4; i++) {          // B: 128 rows x 8 chunks
            int ch = tid + i * THREADS;
            int r = ch >> 3, j = ch & 7;
            cp16(bbuf + r * ROWB + ((j ^ (r & 7)) << 4),
                 Bbase + (size_t)r * K_DIM + k0 + j * 8);
        }
        asm volatile("cp.async.mbarrier.arrive.noinc.shared::cta.b64 [%0];"
                     :: "r"(fullb + 8 * s2) : "memory");
    };

    // ldmatrix lane addressing with XOR swizzle (precomputed)
    const int lq = lane >> 3, lr = lane & 7;
    const uint32_t cba = lq >> 1, cbb = lq & 1;
    uint32_t raoff[2], rboff[4], swzA[4], swzB[4];
#pragma unroll
    for (int i = 0; i < 2; i++)
        raoff[i] = (uint32_t)((wm * 32 + i * 16 + (lq & 1) * 8 + lr) * ROWB);
#pragma unroll
    for (int jp = 0; jp < 4; jp++)
        rboff[jp] = (uint32_t)(A_BYTES + (wn * 64 + jp * 16 + (lq >> 1) * 8 + lr) * ROWB);
#pragma unroll
    for (int ks = 0; ks < 4; ks++) {
        swzA[ks] = (uint32_t)(((2 * ks + cba) ^ lr) << 4);
        swzB[ks] = (uint32_t)(((2 * ks + cbb) ^ lr) << 4);
    }

    float acc[2][8][4];
#pragma unroll
    for (int i = 0; i < 2; i++)
#pragma unroll
        for (int j = 0; j < 8; j++)
#pragma unroll
            for (int r = 0; r < 4; r++) acc[i][j][r] = 0.f;

    produce(0);
    produce(1);

    for (int t = 0; t < KTILES; t++) {
        const int s = t % 3;
        MBAR_WAIT(fullb + 8 * s, (t / 3) & 1);
        const uint32_t stage = sb + s * STAGE_BYTES;

#pragma unroll
        for (int ks = 0; ks < 4; ks++) {
            uint32_t afr[2][4];
#pragma unroll
            for (int i = 0; i < 2; i++)
                ldsm4(afr[i], stage + raoff[i] + swzA[ks]);
            uint32_t bfr[4][4];
#pragma unroll
            for (int jp = 0; jp < 4; jp++)
                ldsm4(bfr[jp], stage + rboff[jp] + swzB[ks]);
            if (ks == 3 && lane == 0)   // all stage reads done for this warp
                asm volatile("mbarrier.arrive.shared::cta.b64 _, [%0];"
                             :: "r"(emptyb + 8 * s) : "memory");
#pragma unroll
            for (int i = 0; i < 2; i++)
#pragma unroll
                for (int j = 0; j < 8; j++)
                    mma_f16(acc[i][j], afr[i], &bfr[j >> 1][(j & 1) * 2]);
        }
        if (t + 2 < KTILES) produce(t + 2);
    }
    __syncthreads();

    // ---- bias add + per-thread partial stats ----
    float psum0[2], psq0[2], psum1[2], psq1[2];
#pragma unroll
    for (int i = 0; i < 2; i++) { psum0[i] = psq0[i] = psum1[i] = psq1[i] = 0.f; }
#pragma unroll
    for (int i = 0; i < 2; i++) {
#pragma unroll
        for (int j = 0; j < 8; j++) {
            const int nc = wn * 64 + j * 8 + 2 * ctid;
            float y0 = acc[i][j][0] + bias_s[nc];
            float y1 = acc[i][j][1] + bias_s[nc + 1];
            float y2 = acc[i][j][2] + bias_s[nc];
            float y3 = acc[i][j][3] + bias_s[nc + 1];
            acc[i][j][0] = y0; acc[i][j][1] = y1; acc[i][j][2] = y2; acc[i][j][3] = y3;
            psum0[i] += y0 + y1;  psq0[i] += y0 * y0 + y1 * y1;
            psum1[i] += y2 + y3;  psq1[i] += y2 * y2 + y3 * y3;
        }
    }
#pragma unroll
    for (int i = 0; i < 2; i++) {
#pragma unroll
        for (int d = 1; d < 4; d <<= 1) {
            psum0[i] += __shfl_xor_sync(0xffffffffu, psum0[i], d);
            psq0[i]  += __shfl_xor_sync(0xffffffffu, psq0[i], d);
            psum1[i] += __shfl_xor_sync(0xffffffffu, psum1[i], d);
            psq1[i]  += __shfl_xor_sync(0xffffffffu, psq1[i], d);
        }
        if (ctid == 0) {
            const int r0 = wm * 32 + i * 16 + gid;
            atomicAdd(&red_s[r0], psum0[i]);
            atomicAdd(&red_s[TILE_M + r0], psq0[i]);
            atomicAdd(&red_s[r0 + 8], psum1[i]);
            atomicAdd(&red_s[TILE_M + r0 + 8], psq1[i]);
        }
    }
    __syncthreads();

    // ---- cluster exchange: combine per-row partials from 3 peers ----
    asm volatile("barrier.cluster.arrive.aligned;" ::: "memory");
    asm volatile("barrier.cluster.wait.aligned;" ::: "memory");

    if (tid < TILE_M) {
        float s  = red_s[tid];
        float sq = red_s[TILE_M + tid];
        const uint32_t lsum = sb + SM_RED + tid * 4;
        const uint32_t lsq  = lsum + TILE_M * 4;
#pragma unroll
        for (int p = 1; p < 4; p++) {
            const uint32_t peer = ((uint32_t)rank + p) & 3u;
            uint32_t rsum, rsq;
            asm("mapa.shared::cluster.u32 %0, %1, %2;" : "=r"(rsum) : "r"(lsum), "r"(peer));
            asm("mapa.shared::cluster.u32 %0, %1, %2;" : "=r"(rsq)  : "r"(lsq),  "r"(peer));
            float ps, pq;
            asm volatile("ld.shared::cluster.f32 %0, [%1];" : "=f"(ps) : "r"(rsum));
            asm volatile("ld.shared::cluster.f32 %0, [%1];" : "=f"(pq) : "r"(rsq));
            s += ps; sq += pq;
        }
        const float mean = s * (1.0f / 512.0f);
        const float var  = fmaxf(sq * (1.0f / 512.0f) - mean * mean, 0.f);
        mean_s[tid] = mean;
        rstd_s[tid] = rsqrtf(var + 1e-5f);
    }
    __syncthreads();
    asm volatile("barrier.cluster.arrive.aligned;" ::: "memory");

    // ---- normalize + SiLU chain + store ----
    float* obase = out + (size_t)(bm * TILE_M) * N_DIM + nbase;
#pragma unroll
    for (int i = 0; i < 2; i++) {
        const int r0 = wm * 32 + i * 16 + gid;
        const float m0 = mean_s[r0],     rs0 = rstd_s[r0];
        const float m1 = mean_s[r0 + 8], rs1 = rstd_s[r0 + 8];
#pragma unroll
        for (int j = 0; j < 8; j++) {
            const int nc = wn * 64 + j * 8 + 2 * ctid;
            const float gw0 = gnw_s[nc], gw1 = gnw_s[nc + 1];
            const float gb0 = gnb_s[nc], gb1 = gnb_s[nc + 1];
            const float w0  = mw_s[nc],  w1  = mw_s[nc + 1];
            float v[4];
            {
                float t0 = (acc[i][j][0] - m0) * rs0 * gw0 + gb0;
                float t1 = (acc[i][j][1] - m0) * rs0 * gw1 + gb1;
                float t2 = (acc[i][j][2] - m1) * rs1 * gw0 + gb0;
                float t3 = (acc[i][j][3] - m1) * rs1 * gw1 + gb1;
                float s0 = t0 / (1.f + __expf(-t0)) * w0;
                float s1 = t1 / (1.f + __expf(-t1)) * w1;
                float s2 = t2 / (1.f + __expf(-t2)) * w0;
                float s3 = t3 / (1.f + __expf(-t3)) * w1;
                v[0] = s0 / (1.f + __expf(-s0));
                v[1] = s1 / (1.f + __expf(-s1));
                v[2] = s2 / (1.f + __expf(-s2));
                v[3] = s3 / (1.f + __expf(-s3));
            }
            float2* p0 = (float2*)(obase + (size_t)r0 * N_DIM + nc);
            float2* p1 = (float2*)(obase + (size_t)(r0 + 8) * N_DIM + nc);
            *p0 = make_float2(v[0], v[1]);
            *p1 = make_float2(v[2], v[3]);
        }
    }

    asm volatile("barrier.cluster.wait.aligned;" ::: "memory");
}

extern "C" void kernel_launch(void* const* d_in, const int* in_sizes, int n_in,
                              void* d_out, int out_size)
{
    const float* x   = (const float*)d_in[0];
    const float* W   = (const float*)d_in[1];
    const float* b   = (const float*)d_in[2];
    const float* gnw = (const float*)d_in[3];
    const float* gnb = (const float*)d_in[4];
    const float* mw  = (const float*)d_in[5];
    float* out = (float*)d_out;

    convert_f32_to_f16<<<2048, 256>>>(x, W);

    cudaFuncSetAttribute(fused_gemm_gn_silu,
                         cudaFuncAttributeMaxDynamicSharedMemorySize, SMEM_TOTAL);
    fused_gemm_gn_silu<<<GRID, THREADS, SMEM_TOTAL>>>(b, gnw, gnb, mw, out);
}

// round 15
// speedup vs baseline: 1.3110x; 1.0107x over previous
#include <cuda_runtime.h>
#include <cuda_fp16.h>
#include <cstdint>

// Fused: out = swish(mult_w * swish(groupnorm(x @ W^T + b)))
// x:[4096,2048] W:[8192,2048] -> out:[4096,8192], 16 groups of 512 features.
//
// R14: producer address algebra. R11 (warp-granular mbarrier pipeline) lifted
// tensor to 65.9% but alu rose to 20.8% -- produce() recomputed 8 cp.async
// addresses per tile. Observation: for ch = tid + 256*i, j=tid&7 and r&7 are
// i-invariant, so the swizzle chunk is per-thread constant and dst/src are
// affine in i with immediate steps. produce() collapses to 2 regs + 8 cp16.
// - CTA tile 128x128, warp tile 32x64, fp16 m16n8k16, fp32 accum, 2 CTAs/SM
// - XOR-swizzled 128B smem rows, 3-stage mbarrier pipeline (full=256, empty=8)
// - cluster of 4 CTAs = one group; stats via DSMEM
// - fp32->fp16 convert pre-pass into __device__ scratch

static constexpr int K_DIM  = 2048;
static constexpr int N_DIM  = 8192;
static constexpr int M_DIM  = 4096;
static constexpr int TILE_M = 128;
static constexpr int TILE_N = 128;
static constexpr int KC     = 64;
static constexpr int KTILES = K_DIM / KC;      // 32
static constexpr int THREADS = 256;
static constexpr int GRID = (M_DIM / TILE_M) * (N_DIM / TILE_N); // 2048

static constexpr int ROWB   = 128;
static constexpr int A_BYTES = TILE_M * ROWB;              // 16384
static constexpr int B_BYTES = TILE_N * ROWB;              // 16384
static constexpr int STAGE_BYTES = A_BYTES + B_BYTES;      // 32768
static constexpr int NSTAGES = 3;

static constexpr int SM_PARAM = NSTAGES * STAGE_BYTES;        // 98304
static constexpr int SM_RED   = SM_PARAM + 4 * TILE_N * 4;    // 100352
static constexpr int SM_STATS = SM_RED + 2 * TILE_M * 4;      // 101376
static constexpr int SM_MBAR  = SM_STATS + 2 * TILE_M * 4;    // 102400
static constexpr int SMEM_TOTAL = SM_MBAR + 64;               // 102464

__device__ __half g_x16[(size_t)M_DIM * K_DIM];   // 16 MB
__device__ __half g_w16[(size_t)N_DIM * K_DIM];   // 32 MB

#define DEVFN __device__ __forceinline__

DEVFN uint32_t s2u(const void* p) {
    uint32_t a;
    asm("{ .reg .u64 t; cvta.to.shared.u64 t, %1; cvt.u32.u64 %0, t; }" : "=r"(a) : "l"(p));
    return a;
}

DEVFN void mma_f16(float c[4], const uint32_t a[4], const uint32_t b[2]) {
    asm volatile(
        "mma.sync.aligned.m16n8k16.row.col.f32.f16.f16.f32 "
        "{%0,%1,%2,%3}, {%4,%5,%6,%7}, {%8,%9}, {%0,%1,%2,%3};"
        : "+f"(c[0]), "+f"(c[1]), "+f"(c[2]), "+f"(c[3])
        : "r"(a[0]), "r"(a[1]), "r"(a[2]), "r"(a[3]), "r"(b[0]), "r"(b[1]));
}

DEVFN void ldsm4(uint32_t r[4], uint32_t addr) {
    asm volatile(
        "ldmatrix.sync.aligned.m8n8.x4.shared.b16 {%0,%1,%2,%3}, [%4];"
        : "=r"(r[0]), "=r"(r[1]), "=r"(r[2]), "=r"(r[3]) : "r"(addr));
}

DEVFN void cp16(uint32_t dst, const void* src) {
    asm volatile("cp.async.cg.shared.global [%0], [%1], 16;" :: "r"(dst), "l"(src));
}

#define MBAR_INIT(addr, cnt) \
    asm volatile("mbarrier.init.shared.b64 [%0], %1;" :: "r"(addr), "r"((uint32_t)(cnt)) : "memory")

#define MBAR_WAIT(addr, parity) do { \
    asm volatile( \
        "{\n\t" \
        ".reg .pred P1;\n\t" \
        "WAIT_%=:\n\t" \
        "mbarrier.try_wait.parity.acquire.cta.shared::cta.b64 P1, [%0], %1, 0x989680;\n\t" \
        "@P1 bra.uni DONE_%=;\n\t" \
        "bra.uni WAIT_%=;\n\t" \
        "DONE_%=:\n\t" \
        "}" \
        :: "r"(addr), "r"((uint32_t)(parity)) : "memory"); \
} while (0)

// ---- pre-pass: fp32 -> fp16 for x and W ----
__global__ void __launch_bounds__(256)
convert_f32_to_f16(const float* __restrict__ x, const float* __restrict__ W)
{
    const size_t XN4 = (size_t)M_DIM * K_DIM / 4;
    const size_t WN4 = (size_t)N_DIM * K_DIM / 4;
    const size_t total = XN4 + WN4;
    const size_t stride = (size_t)gridDim.x * blockDim.x;
    for (size_t i = (size_t)blockIdx.x * blockDim.x + threadIdx.x; i < total; i += stride) {
        float4 v;
        __half2* dst;
        if (i < XN4) {
            v = ((const float4*)x)[i];
            dst = (__half2*)g_x16 + i * 2;
        } else {
            v = ((const float4*)W)[i - XN4];
            dst = (__half2*)g_w16 + (i - XN4) * 2;
        }
        dst[0] = __floats2half2_rn(v.x, v.y);
        dst[1] = __floats2half2_rn(v.z, v.w);
    }
}

__global__ void __launch_bounds__(THREADS, 2) __cluster_dims__(4, 1, 1)
fused_gemm_gn_silu(const float* __restrict__ b, const float* __restrict__ gnw,
                   const float* __restrict__ gnb, const float* __restrict__ mw,
                   float* __restrict__ out)
{
    extern __shared__ char smem[];
    const uint32_t sb = s2u(smem);
    const int tid  = threadIdx.x;
    const int wid  = tid >> 5, lane = tid & 31;
    const int gid  = lane >> 2, ctid = lane & 3;
    const int wm   = wid & 3;        // 0..3 : 32-row band
    const int wn   = wid >> 2;       // 0..1 : 64-col band

    const int bx   = blockIdx.x;
    const int rank = bx & 3;                 // cluster rank = N quarter
    const int bm   = (bx >> 2) & 31;         // M block
    const int g    = bx >> 7;                // group 0..15
    const int nbase = g * 512 + rank * TILE_N;

    float* bias_s = (float*)(smem + SM_PARAM);
    float* gnw_s  = bias_s + TILE_N;
    float* gnb_s  = gnw_s + TILE_N;
    float* mw_s   = gnb_s + TILE_N;
    float* red_s  = (float*)(smem + SM_RED);
    float* mean_s = (float*)(smem + SM_STATS);
    float* rstd_s = mean_s + TILE_M;

    const uint32_t fullb  = sb + SM_MBAR;       // 3 x 8B
    const uint32_t emptyb = sb + SM_MBAR + 24;  // 3 x 8B

    if (tid == 0) {
#pragma unroll
        for (int s = 0; s < 3; s++) {
            MBAR_INIT(fullb + 8 * s, THREADS);
            MBAR_INIT(emptyb + 8 * s, 8);
        }
    }
    if (tid < TILE_N) {
        bias_s[tid] = b[nbase + tid];
        gnw_s[tid]  = gnw[nbase + tid];
        gnb_s[tid]  = gnb[nbase + tid];
        mw_s[tid]   = mw[nbase + tid];
    }
    red_s[tid] = 0.f;
    __syncthreads();

    // producer addressing, collapsed:
    //   ch = tid + 256*i  ->  j = tid&7 (i-invariant), r = (tid>>3) + 32*i,
    //   r&7 = (tid>>3)&7 (i-invariant)  ->  swizzle chunk constant per thread.
    //   dst(i) = r0*128 + ((j^(r0&7))<<4) + i*4096
    //   src(i) = r0*4096 + j*16 + i*131072 + k0*2     (byte offsets)
    const uint32_t r0 = (uint32_t)tid >> 3;
    const uint32_t j0 = (uint32_t)tid & 7;
    const uint32_t dst0 = r0 * ROWB + ((j0 ^ (r0 & 7)) << 4);
    const uint32_t src0 = r0 * (K_DIM * 2) + j0 * 16;

    const char* Abase = (const char*)(g_x16 + (size_t)bm * TILE_M * K_DIM) + src0;
    const char* Bbase = (const char*)(g_w16 + (size_t)nbase * K_DIM) + src0;

    auto produce = [&](int u) {
        const int s2 = u % 3;
        if (u >= 3) MBAR_WAIT(emptyb + 8 * s2, ((u / 3 - 1) & 1));
        const uint32_t k0b = (uint32_t)u * (KC * 2);
        const uint32_t abuf = sb + s2 * STAGE_BYTES + dst0;
        const uint32_t bbuf = abuf + A_BYTES;
        const char* asrc = Abase + k0b;
        const char* bsrc = Bbase + k0b;
#pragma unroll
        for (int i = 0; i < 4; i++)
            cp16(abuf + i * 4096, asrc + i * 131072);
#pragma unroll
        for (int i = 0; i < 4; i++)
            cp16(bbuf + i * 4096, bsrc + i * 131072);
        asm volatile("cp.async.mbarrier.arrive.noinc.shared::cta.b64 [%0];"
                     :: "r"(fullb + 8 * s2) : "memory");
    };

    // ldmatrix lane addressing with XOR swizzle (precomputed)
    const int lq = lane >> 3, lr = lane & 7;
    const uint32_t cba = lq >> 1, cbb = lq & 1;
    uint32_t raoff[2], rboff[4], swzA[4], swzB[4];
#pragma unroll
    for (int i = 0; i < 2; i++)
        raoff[i] = (uint32_t)((wm * 32 + i * 16 + (lq & 1) * 8 + lr) * ROWB);
#pragma unroll
    for (int jp = 0; jp < 4; jp++)
        rboff[jp] = (uint32_t)(A_BYTES + (wn * 64 + jp * 16 + (lq >> 1) * 8 + lr) * ROWB);
#pragma unroll
    for (int ks = 0; ks < 4; ks++) {
        swzA[ks] = (uint32_t)(((2 * ks + cba) ^ lr) << 4);
        swzB[ks] = (uint32_t)(((2 * ks + cbb) ^ lr) << 4);
    }

    float acc[2][8][4];
#pragma unroll
    for (int i = 0; i < 2; i++)
#pragma unroll
        for (int j = 0; j < 8; j++)
#pragma unroll
            for (int r = 0; r < 4; r++) acc[i][j][r] = 0.f;

    produce(0);
    produce(1);

    for (int t = 0; t < KTILES; t++) {
        const int s = t % 3;
        MBAR_WAIT(fullb + 8 * s, (t / 3) & 1);
        const uint32_t stage = sb + s * STAGE_BYTES;

#pragma unroll
        for (int ks = 0; ks < 4; ks++) {
            uint32_t afr[2][4];
#pragma unroll
            for (int i = 0; i < 2; i++)
                ldsm4(afr[i], stage + raoff[i] + swzA[ks]);
            uint32_t bfr[4][4];
#pragma unroll
            for (int jp = 0; jp < 4; jp++)
                ldsm4(bfr[jp], stage + rboff[jp] + swzB[ks]);
            if (ks == 3 && lane == 0)
                asm volatile("mbarrier.arrive.shared::cta.b64 _, [%0];"
                             :: "r"(emptyb + 8 * s) : "memory");
#pragma unroll
            for (int i = 0; i < 2; i++)
#pragma unroll
                for (int j = 0; j < 8; j++)
                    mma_f16(acc[i][j], afr[i], &bfr[j >> 1][(j & 1) * 2]);
        }
        if (t + 2 < KTILES) produce(t + 2);
    }
    __syncthreads();

    // ---- bias add + per-thread partial stats ----
    float psum0[2], psq0[2], psum1[2], psq1[2];
#pragma unroll
    for (int i = 0; i < 2; i++) { psum0[i] = psq0[i] = psum1[i] = psq1[i] = 0.f; }
#pragma unroll
    for (int i = 0; i < 2; i++) {
#pragma unroll
        for (int j = 0; j < 8; j++) {
            const int nc = wn * 64 + j * 8 + 2 * ctid;
            float y0 = acc[i][j][0] + bias_s[nc];
            float y1 = acc[i][j][1] + bias_s[nc + 1];
            float y2 = acc[i][j][2] + bias_s[nc];
            float y3 = acc[i][j][3] + bias_s[nc + 1];
            acc[i][j][0] = y0; acc[i][j][1] = y1; acc[i][j][2] = y2; acc[i][j][3] = y3;
            psum0[i] += y0 + y1;  psq0[i] += y0 * y0 + y1 * y1;
            psum1[i] += y2 + y3;  psq1[i] += y2 * y2 + y3 * y3;
        }
    }
#pragma unroll
    for (int i = 0; i < 2; i++) {
#pragma unroll
        for (int d = 1; d < 4; d <<= 1) {
            psum0[i] += __shfl_xor_sync(0xffffffffu, psum0[i], d);
            psq0[i]  += __shfl_xor_sync(0xffffffffu, psq0[i], d);
            psum1[i] += __shfl_xor_sync(0xffffffffu, psum1[i], d);
            psq1[i]  += __shfl_xor_sync(0xffffffffu, psq1[i], d);
        }
        if (ctid == 0) {
            const int r0i = wm * 32 + i * 16 + gid;
            atomicAdd(&red_s[r0i], psum0[i]);
            atomicAdd(&red_s[TILE_M + r0i], psq0[i]);
            atomicAdd(&red_s[r0i + 8], psum1[i]);
            atomicAdd(&red_s[TILE_M + r0i + 8], psq1[i]);
        }
    }
    __syncthreads();

    // ---- cluster exchange: combine per-row partials from 3 peers ----
    asm volatile("barrier.cluster.arrive.aligned;" ::: "memory");
    asm volatile("barrier.cluster.wait.aligned;" ::: "memory");

    if (tid < TILE_M) {
        float s  = red_s[tid];
        float sq = red_s[TILE_M + tid];
        const uint32_t lsum = sb + SM_RED + tid * 4;
        const uint32_t lsq  = lsum + TILE_M * 4;
#pragma unroll
        for (int p = 1; p < 4; p++) {
            const uint32_t peer = ((uint32_t)rank + p) & 3u;
            uint32_t rsum, rsq;
            asm("mapa.shared::cluster.u32 %0, %1, %2;" : "=r"(rsum) : "r"(lsum), "r"(peer));
            asm("mapa.shared::cluster.u32 %0, %1, %2;" : "=r"(rsq)  : "r"(lsq),  "r"(peer));
            float ps, pq;
            asm volatile("ld.shared::cluster.f32 %0, [%1];" : "=f"(ps) : "r"(rsum));
            asm volatile("ld.shared::cluster.f32 %0, [%1];" : "=f"(pq) : "r"(rsq));
            s += ps; sq += pq;
        }
        const float mean = s * (1.0f / 512.0f);
        const float var  = fmaxf(sq * (1.0f / 512.0f) - mean * mean, 0.f);
        mean_s[tid] = mean;
        rstd_s[tid] = rsqrtf(var + 1e-5f);
    }
    __syncthreads();
    asm volatile("barrier.cluster.arrive.aligned;" ::: "memory");

    // ---- normalize + SiLU chain + store ----
    float* obase = out + (size_t)(bm * TILE_M) * N_DIM + nbase;
#pragma unroll
    for (int i = 0; i < 2; i++) {
        const int r0i = wm * 32 + i * 16 + gid;
        const float m0 = mean_s[r0i],     rs0 = rstd_s[r0i];
        const float m1 = mean_s[r0i + 8], rs1 = rstd_s[r0i + 8];
#pragma unroll
        for (int j = 0; j < 8; j++) {
            const int nc = wn * 64 + j * 8 + 2 * ctid;
            const float gw0 = gnw_s[nc], gw1 = gnw_s[nc + 1];
            const float gb0 = gnb_s[nc], gb1 = gnb_s[nc + 1];
            const float w0  = mw_s[nc],  w1  = mw_s[nc + 1];
            float v[4];
            {
                float t0 = (acc[i][j][0] - m0) * rs0 * gw0 + gb0;
                float t1 = (acc[i][j][1] - m0) * rs0 * gw1 + gb1;
                float t2 = (acc[i][j][2] - m1) * rs1 * gw0 + gb0;
                float t3 = (acc[i][j][3] - m1) * rs1 * gw1 + gb1;
                float s0 = t0 / (1.f + __expf(-t0)) * w0;
                float s1 = t1 / (1.f + __expf(-t1)) * w1;
                float s2 = t2 / (1.f + __expf(-t2)) * w0;
                float s3 = t3 / (1.f + __expf(-t3)) * w1;
                v[0] = s0 / (1.f + __expf(-s0));
                v[1] = s1 / (1.f + __expf(-s1));
                v[2] = s2 / (1.f + __expf(-s2));
                v[3] = s3 / (1.f + __expf(-s3));
            }
            float2* p0 = (float2*)(obase + (size_t)r0i * N_DIM + nc);
            float2* p1 = (float2*)(obase + (size_t)(r0i + 8) * N_DIM + nc);
            *p0 = make_float2(v[0], v[1]);
            *p1 = make_float2(v[2], v[3]);
        }
    }

    asm volatile("barrier.cluster.wait.aligned;" ::: "memory");
}

extern "C" void kernel_launch(void* const* d_in, const int* in_sizes, int n_in,
                              void* d_out, int out_size)
{
    const float* x   = (const float*)d_in[0];
    const float* W   = (const float*)d_in[1];
    const float* b   = (const float*)d_in[2];
    const float* gnw = (const float*)d_in[3];
    const float* gnb = (const float*)d_in[4];
    const float* mw  = (const float*)d_in[5];
    float* out = (float*)d_out;

    convert_f32_to_f16<<<2048, 256>>>(x, W);

    cudaFuncSetAttribute(fused_gemm_gn_silu,
                         cudaFuncAttributeMaxDynamicSharedMemorySize, SMEM_TOTAL);
    fused_gemm_gn_silu<<<GRID, THREADS, SMEM_TOTAL>>>(b, gnw, gnb, mw, out);
}